// round 15
// baseline (speedup 1.0000x reference)
#include <cuda_runtime.h>
#include <math.h>

#define BATCH 2
#define SEQ   2000
#define DM    256
#define DI    512
#define DS    16
#define DTR   16
#define NXP   (DTR + 2*DS)   /* 48 */
#define NT    (BATCH*SEQ)    /* 4000 */
#define NL    4
#define NCHUNK 16
#define CLEN  (SEQ / NCHUNK)  /* 125 */

// ---------------- scratch (static device globals; no allocation) ----------------
static __device__ float g_h   [NT*DM];        // residual stream
static __device__ float g_hn  [NT*DM];        // layernormed h
static __device__ float g_xz  [NT*2*DI];      // in_proj output (u | z)
static __device__ float g_u   [NT*DI];        // post-conv + silu
static __device__ float g_xdbc[NT*NXP];       // x_proj output (dt_r | B | C)
static __device__ float g_dt  [NT*DI];        // softplus(dt)
static __device__ float g_y   [NT*DI];        // scan output (gated)
// chunked-scan carries: [chunk][b][d][n]
static __device__ float g_aprod[NCHUNK*BATCH*DI*DS];
static __device__ float g_send [NCHUNK*BATCH*DI*DS];

// ---------------- helpers ----------------
__device__ __forceinline__ float blockReduceSum256(float v) {
    __shared__ float sh[8];
    __shared__ float total;
    #pragma unroll
    for (int o = 16; o > 0; o >>= 1) v += __shfl_xor_sync(0xffffffffu, v, o);
    if ((threadIdx.x & 31) == 0) sh[threadIdx.x >> 5] = v;
    __syncthreads();
    if (threadIdx.x == 0) {
        float s = 0.f;
        #pragma unroll
        for (int i = 0; i < 8; i++) s += sh[i];
        total = s;
    }
    __syncthreads();
    return total;
}

// ---------------- kernels ----------------

// h = x[...,None]*w + b + gene_emb + mod_emb
__global__ void embed_kernel(const float* __restrict__ x,
                             const float* __restrict__ w,
                             const float* __restrict__ b,
                             const float* __restrict__ ge,
                             const float* __restrict__ me) {
    int i = blockIdx.x * 256 + threadIdx.x;
    if (i >= NT * DM) return;
    int d = i & (DM - 1);
    int t = i >> 8;
    int l = t % SEQ;
    g_h[i] = x[t] * w[d] + b[d] + ge[l * DM + d] + me[d];
}

// LayerNorm over last dim (256); one block per token
__global__ void ln_kernel(const float* __restrict__ in, float* __restrict__ out,
                          const float* __restrict__ w, const float* __restrict__ b) {
    int t = blockIdx.x, d = threadIdx.x;
    float v = in[t * DM + d];
    float mean = blockReduceSum256(v) * (1.f / DM);
    float diff = v - mean;
    float var = blockReduceSum256(diff * diff) * (1.f / DM);
    out[t * DM + d] = diff * rsqrtf(var + 1e-5f) * w[d] + b[d];
}

// ---------------- SGEMM (spill-safe tiles) ----------------
// C[M,N] = A[M,K] @ W[N,K]^T, optional accumulate.
// 256 threads; micro-tile (BM/16)x(BN/16); register prefetch of next k-tile.
template<int BM, int BN, int ACCUM>
__global__ void __launch_bounds__(256)
sgemm_nt2(const float* __restrict__ A, const float* __restrict__ W,
          float* __restrict__ C, int M, int N, int K) {
    constexpr int BK = 16;
    constexpr int TM = BM / 16, TN = BN / 16;
    constexpr int NAL = BM / 64, NWL = BN / 64;
    __shared__ float As[BK][BM + 4];
    __shared__ float Ws[BK][BN + 4];

    const int tid = threadIdx.x;
    const int m0 = blockIdx.y * BM, n0 = blockIdx.x * BN;
    const int tx = tid & 15, ty = tid >> 4;
    const int lr = tid >> 2;             // 0..63
    const int lc = tid & 3;              // k-group (offset lc*4)

    float acc[TM][TN];
    #pragma unroll
    for (int i = 0; i < TM; i++)
        #pragma unroll
        for (int j = 0; j < TN; j++) acc[i][j] = 0.f;

    const float4 f4z = make_float4(0.f, 0.f, 0.f, 0.f);
    float4 pa[NAL], pw[NWL];

    // prefetch k-tile 0
    #pragma unroll
    for (int q = 0; q < NAL; q++) {
        int r = m0 + lr + 64 * q;
        pa[q] = (r < M) ? *reinterpret_cast<const float4*>(A + (size_t)r * K + lc * 4) : f4z;
    }
    #pragma unroll
    for (int q = 0; q < NWL; q++)
        pw[q] = *reinterpret_cast<const float4*>(W + (size_t)(n0 + lr + 64 * q) * K + lc * 4);

    for (int kt = 0; kt < K; kt += BK) {
        #pragma unroll
        for (int q = 0; q < NAL; q++) {
            As[lc * 4 + 0][lr + 64 * q] = pa[q].x;
            As[lc * 4 + 1][lr + 64 * q] = pa[q].y;
            As[lc * 4 + 2][lr + 64 * q] = pa[q].z;
            As[lc * 4 + 3][lr + 64 * q] = pa[q].w;
        }
        #pragma unroll
        for (int q = 0; q < NWL; q++) {
            Ws[lc * 4 + 0][lr + 64 * q] = pw[q].x;
            Ws[lc * 4 + 1][lr + 64 * q] = pw[q].y;
            Ws[lc * 4 + 2][lr + 64 * q] = pw[q].z;
            Ws[lc * 4 + 3][lr + 64 * q] = pw[q].w;
        }
        __syncthreads();

        if (kt + BK < K) {
            int kn = kt + BK;
            #pragma unroll
            for (int q = 0; q < NAL; q++) {
                int r = m0 + lr + 64 * q;
                pa[q] = (r < M) ? *reinterpret_cast<const float4*>(A + (size_t)r * K + kn + lc * 4) : f4z;
            }
            #pragma unroll
            for (int q = 0; q < NWL; q++)
                pw[q] = *reinterpret_cast<const float4*>(W + (size_t)(n0 + lr + 64 * q) * K + kn + lc * 4);
        }

        #pragma unroll
        for (int kk = 0; kk < BK; kk++) {
            float a[TM], w[TN];
            #pragma unroll
            for (int i4 = 0; i4 < TM; i4 += 4) {
                float4 v = *reinterpret_cast<const float4*>(&As[kk][ty * TM + i4]);
                a[i4 + 0] = v.x; a[i4 + 1] = v.y; a[i4 + 2] = v.z; a[i4 + 3] = v.w;
            }
            #pragma unroll
            for (int j4 = 0; j4 < TN; j4 += 4) {
                float4 v = *reinterpret_cast<const float4*>(&Ws[kk][tx * TN + j4]);
                w[j4 + 0] = v.x; w[j4 + 1] = v.y; w[j4 + 2] = v.z; w[j4 + 3] = v.w;
            }
            #pragma unroll
            for (int i = 0; i < TM; i++)
                #pragma unroll
                for (int j = 0; j < TN; j++)
                    acc[i][j] = fmaf(a[i], w[j], acc[i][j]);
        }
        __syncthreads();
    }

    #pragma unroll
    for (int i = 0; i < TM; i++) {
        int m = m0 + ty * TM + i;
        if (m >= M) continue;
        float* cr = C + (size_t)m * N + n0 + tx * TN;
        #pragma unroll
        for (int j4 = 0; j4 < TN; j4 += 4) {
            float4 v = make_float4(acc[i][j4], acc[i][j4 + 1], acc[i][j4 + 2], acc[i][j4 + 3]);
            if (ACCUM) {
                float4 o = *reinterpret_cast<const float4*>(cr + j4);
                v.x += o.x; v.y += o.y; v.z += o.z; v.w += o.w;
            }
            *reinterpret_cast<float4*>(cr + j4) = v;
        }
    }
}

// Depthwise causal conv (D_CONV=4) over u-half of xz, + bias, + SiLU
__global__ void conv_silu_kernel(const float* __restrict__ cw,
                                 const float* __restrict__ cb) {
    int idx = blockIdx.x * 256 + threadIdx.x;
    if (idx >= NT * DI) return;
    int d = idx & (DI - 1);
    int t = idx >> 9;
    int l = t % SEQ;
    float s = cb[d];
    #pragma unroll
    for (int k = 0; k < 4; k++) {
        int ls = l + k - 3;
        if (ls >= 0) s = fmaf(g_xz[(size_t)(t - l + ls) * (2 * DI) + d], cw[d * 4 + k], s);
    }
    g_u[idx] = s / (1.f + __expf(-s));
}

// ---------------- xproj as a tiled GEMM ----------------
// xdbc[M=4000, N=48] = u[M, K=512] @ xpw[N=48, K]^T
// BM=64 tokens, BN=48 (full), BK=64. Weights staged in smem once per 64 tokens.
__global__ void __launch_bounds__(256)
xproj_gemm(const float* __restrict__ xpw) {
    constexpr int BM = 64, BK = 64;
    __shared__ float As[BK][BM + 4];     // u, transposed
    __shared__ float Ws[BK][NXP + 4];    // weights, transposed

    const int tid = threadIdx.x;
    const int m0 = blockIdx.x * BM;
    const int tx = tid & 15;             // n-group: 3 cols each
    const int ty = tid >> 4;             // row-group: 4 rows each

    float acc[4][3];
    #pragma unroll
    for (int i = 0; i < 4; i++)
        #pragma unroll
        for (int j = 0; j < 3; j++) acc[i][j] = 0.f;

    const int lr = tid >> 2;             // 0..63 (A row)
    const int lc = tid & 3;              // float4 group base

    for (int kt = 0; kt < DI; kt += BK) {
        // A tile: 64 rows x 64 k = 1024 float4; 4 per thread
        #pragma unroll
        for (int j = 0; j < 4; j++) {
            int m = m0 + lr;
            int kb = (lc * 4 + j) * 4;   // 0..60 step 4
            float4 v = (m < NT)
                ? *reinterpret_cast<const float4*>(g_u + (size_t)m * DI + kt + kb)
                : make_float4(0.f, 0.f, 0.f, 0.f);
            As[kb + 0][lr] = v.x;
            As[kb + 1][lr] = v.y;
            As[kb + 2][lr] = v.z;
            As[kb + 3][lr] = v.w;
        }
        // W tile: 48 rows x 64 k = 768 float4; 3 per thread
        for (int idx = tid; idx < NXP * 16; idx += 256) {
            int n = idx >> 4;
            int kb = (idx & 15) * 4;
            float4 v = *reinterpret_cast<const float4*>(xpw + (size_t)n * DI + kt + kb);
            Ws[kb + 0][n] = v.x;
            Ws[kb + 1][n] = v.y;
            Ws[kb + 2][n] = v.z;
            Ws[kb + 3][n] = v.w;
        }
        __syncthreads();

        #pragma unroll
        for (int kk = 0; kk < BK; kk++) {
            float a0 = As[kk][ty * 4 + 0];
            float a1 = As[kk][ty * 4 + 1];
            float a2 = As[kk][ty * 4 + 2];
            float a3 = As[kk][ty * 4 + 3];
            float w0 = Ws[kk][tx * 3 + 0];
            float w1 = Ws[kk][tx * 3 + 1];
            float w2 = Ws[kk][tx * 3 + 2];
            acc[0][0] = fmaf(a0, w0, acc[0][0]);
            acc[0][1] = fmaf(a0, w1, acc[0][1]);
            acc[0][2] = fmaf(a0, w2, acc[0][2]);
            acc[1][0] = fmaf(a1, w0, acc[1][0]);
            acc[1][1] = fmaf(a1, w1, acc[1][1]);
            acc[1][2] = fmaf(a1, w2, acc[1][2]);
            acc[2][0] = fmaf(a2, w0, acc[2][0]);
            acc[2][1] = fmaf(a2, w1, acc[2][1]);
            acc[2][2] = fmaf(a2, w2, acc[2][2]);
            acc[3][0] = fmaf(a3, w0, acc[3][0]);
            acc[3][1] = fmaf(a3, w1, acc[3][1]);
            acc[3][2] = fmaf(a3, w2, acc[3][2]);
        }
        __syncthreads();
    }

    #pragma unroll
    for (int i = 0; i < 4; i++) {
        int m = m0 + ty * 4 + i;
        if (m >= NT) continue;
        #pragma unroll
        for (int j = 0; j < 3; j++)
            g_xdbc[(size_t)m * NXP + tx * 3 + j] = acc[i][j];
    }
}

// dt[t,d] = softplus( xdbc[t,:16] . dtw[d,:] + dtb[d] )
__global__ void dt_kernel(const float* __restrict__ dtw,
                          const float* __restrict__ dtb) {
    int idx = blockIdx.x * 256 + threadIdx.x;
    if (idx >= NT * DI) return;
    int d = idx & (DI - 1);
    int t = idx >> 9;
    const float* r = g_xdbc + (size_t)t * NXP;
    const float* w = dtw + (size_t)d * DTR;
    float s = dtb[d];
    #pragma unroll
    for (int k = 0; k < DTR; k++) s = fmaf(r[k], w[k], s);
    g_dt[idx] = (s > 20.f) ? s : log1pf(__expf(s));
}

// ---- chunked selective scan ----
// Pass 1: per chunk compute (prod dA, local scan end) with zero initial state.
__global__ void scan_pass1(const float* __restrict__ A_log) {
    int gid = blockIdx.x * 256 + threadIdx.x;   // 262144 threads
    int n = gid & 15;
    int r = gid >> 4;
    int d = r & (DI - 1);
    int b = (r >> 9) & (BATCH - 1);
    int c = r >> 10;
    const float Ac = -__expf(A_log[d * DS + n]);
    float state = 0.f, aprod = 1.f;
    const int t0 = b * SEQ + c * CLEN;
    #pragma unroll 5
    for (int l = 0; l < CLEN; l++) {
        int t = t0 + l;
        float dtv = g_dt[(size_t)t * DI + d];
        float uv  = g_u [(size_t)t * DI + d];
        float Bv  = g_xdbc[(size_t)t * NXP + DTR + n];
        float dA = __expf(dtv * Ac);
        aprod *= dA;
        state = fmaf(dA, state, dtv * Bv * uv);
    }
    int idx = ((c * BATCH + b) * DI + d) * DS + n;
    g_aprod[idx] = aprod;
    g_send[idx]  = state;
}

// Pass 2: recompute carry-in prefix inline (<=15 fma), rescan chunk, emit gated y.
__global__ void scan_pass2(const float* __restrict__ A_log,
                           const float* __restrict__ Dv) {
    int gid = blockIdx.x * 256 + threadIdx.x;   // 262144 threads
    int n = gid & 15;
    int r = gid >> 4;
    int d = r & (DI - 1);
    int b = (r >> 9) & (BATCH - 1);
    int c = r >> 10;
    const float Ac = -__expf(A_log[d * DS + n]);
    const float Dd = Dv[d];

    float state = 0.f;
    for (int cc = 0; cc < c; cc++) {
        int idx = ((cc * BATCH + b) * DI + d) * DS + n;
        state = fmaf(g_aprod[idx], state, g_send[idx]);
    }

    const int t0 = b * SEQ + c * CLEN;
    #pragma unroll 5
    for (int l = 0; l < CLEN; l++) {
        int t = t0 + l;
        float dtv = g_dt[(size_t)t * DI + d];
        float uv  = g_u [(size_t)t * DI + d];
        float Bv  = g_xdbc[(size_t)t * NXP + DTR + n];
        float Cv  = g_xdbc[(size_t)t * NXP + DTR + DS + n];
        float dA = __expf(dtv * Ac);
        state = fmaf(dA, state, dtv * Bv * uv);
        float p = state * Cv;
        p += __shfl_xor_sync(0xffffffffu, p, 1, 16);
        p += __shfl_xor_sync(0xffffffffu, p, 2, 16);
        p += __shfl_xor_sync(0xffffffffu, p, 4, 16);
        p += __shfl_xor_sync(0xffffffffu, p, 8, 16);
        if (n == 0) {
            float z = g_xz[(size_t)t * (2 * DI) + DI + d];
            g_y[(size_t)t * DI + d] = (p + uv * Dd) * (z / (1.f + __expf(-z)));
        }
    }
}

// Final LN + head dot product; one block per token
__global__ void final_kernel(const float* __restrict__ fw, const float* __restrict__ fb,
                             const float* __restrict__ hw, const float* __restrict__ hb,
                             float* __restrict__ out) {
    int t = blockIdx.x, d = threadIdx.x;
    float v = g_h[t * DM + d];
    float mean = blockReduceSum256(v) * (1.f / DM);
    float diff = v - mean;
    float var = blockReduceSum256(diff * diff) * (1.f / DM);
    float nr = diff * rsqrtf(var + 1e-5f) * fw[d] + fb[d];
    float s = blockReduceSum256(nr * hw[d]);
    if (d == 0) out[t] = s + hb[0];
}

// ---------------- launch ----------------
extern "C" void kernel_launch(void* const* d_in, const int* in_sizes, int n_in,
                              void* d_out, int out_size) {
    const float* x         = (const float*)d_in[0];
    const float* bulk_in_w = (const float*)d_in[1];
    const float* bulk_in_b = (const float*)d_in[2];
    const float* gene_emb  = (const float*)d_in[3];
    const float* mod_emb   = (const float*)d_in[4];
    const float* ln_w      = (const float*)d_in[5];
    const float* ln_b      = (const float*)d_in[6];
    const float* in_proj_w = (const float*)d_in[7];
    const float* conv_w    = (const float*)d_in[8];
    const float* conv_b    = (const float*)d_in[9];
    const float* x_proj_w  = (const float*)d_in[10];
    const float* dt_proj_w = (const float*)d_in[11];
    const float* dt_proj_b = (const float*)d_in[12];
    const float* A_log     = (const float*)d_in[13];
    const float* Dvec      = (const float*)d_in[14];
    const float* out_proj_w= (const float*)d_in[15];
    const float* fin_w     = (const float*)d_in[16];
    const float* fin_b     = (const float*)d_in[17];
    const float* head_w    = (const float*)d_in[18];
    const float* head_b    = (const float*)d_in[19];
    float* out = (float*)d_out;

    float *p_h, *p_hn, *p_xz, *p_y;
    cudaGetSymbolAddress((void**)&p_h,  g_h);
    cudaGetSymbolAddress((void**)&p_hn, g_hn);
    cudaGetSymbolAddress((void**)&p_xz, g_xz);
    cudaGetSymbolAddress((void**)&p_y,  g_y);

    embed_kernel<<<(NT * DM + 255) / 256, 256>>>(x, bulk_in_w, bulk_in_b, gene_emb, mod_emb);

    for (int i = 0; i < NL; i++) {
        ln_kernel<<<NT, 256>>>(p_h, p_hn, ln_w + i * DM, ln_b + i * DM);

        // xz = hn @ in_proj_w^T   (M=4000, N=1024, K=256)  [128x64 tiles]
        sgemm_nt2<128, 64, 0><<<dim3((2 * DI) / 64, (NT + 127) / 128), 256>>>(
            p_hn, in_proj_w + (size_t)i * (2 * DI) * DM, p_xz, NT, 2 * DI, DM);

        conv_silu_kernel<<<(NT * DI + 255) / 256, 256>>>(conv_w + (size_t)i * DI * 4,
                                                         conv_b + (size_t)i * DI);

        xproj_gemm<<<(NT + 63) / 64, 256>>>(x_proj_w + (size_t)i * NXP * DI);

        dt_kernel<<<(NT * DI + 255) / 256, 256>>>(dt_proj_w + (size_t)i * DI * DTR,
                                                  dt_proj_b + (size_t)i * DI);

        scan_pass1<<<(BATCH * DI * DS * NCHUNK) / 256, 256>>>(A_log + (size_t)i * DI * DS);
        scan_pass2<<<(BATCH * DI * DS * NCHUNK) / 256, 256>>>(A_log + (size_t)i * DI * DS,
                                                              Dvec + (size_t)i * DI);

        // h += y @ out_proj_w^T   (M=4000, N=256, K=512)  [64x64 tiles]
        sgemm_nt2<64, 64, 1><<<dim3(DM / 64, (NT + 63) / 64), 256>>>(
            p_y, out_proj_w + (size_t)i * DM * DI, p_h, NT, DM, DI);
    }

    final_kernel<<<NT, 256>>>(fin_w, fin_b, head_w, head_b, out);
}

// round 16
// speedup vs baseline: 1.2151x; 1.2151x over previous
#include <cuda_runtime.h>
#include <math.h>

#define BATCH 2
#define SEQ   2000
#define DM    256
#define DI    512
#define DS    16
#define DTR   16
#define NXP   (DTR + 2*DS)   /* 48 */
#define NT    (BATCH*SEQ)    /* 4000 */
#define NL    4
#define NCHUNK 16
#define CLEN  (SEQ / NCHUNK)  /* 125 */

// ---------------- scratch (static device globals; no allocation) ----------------
static __device__ float g_h   [NT*DM];        // residual stream
static __device__ float g_hn  [NT*DM];        // layernormed h
static __device__ float g_xz  [NT*2*DI];      // in_proj output (u | z)
static __device__ float g_u   [NT*DI];        // post-conv + silu
static __device__ float g_xdbc[NT*NXP];       // x_proj output (dt_r | B | C)
static __device__ float g_dt  [NT*DI];        // softplus(dt)
static __device__ float g_y   [NT*DI];        // scan output (gated)

// ---------------- helpers ----------------
__device__ __forceinline__ float blockReduceSum256(float v) {
    __shared__ float sh[8];
    __shared__ float total;
    #pragma unroll
    for (int o = 16; o > 0; o >>= 1) v += __shfl_xor_sync(0xffffffffu, v, o);
    if ((threadIdx.x & 31) == 0) sh[threadIdx.x >> 5] = v;
    __syncthreads();
    if (threadIdx.x == 0) {
        float s = 0.f;
        #pragma unroll
        for (int i = 0; i < 8; i++) s += sh[i];
        total = s;
    }
    __syncthreads();
    return total;
}

// ---------------- kernels ----------------

// h = x[...,None]*w + b + gene_emb + mod_emb
__global__ void embed_kernel(const float* __restrict__ x,
                             const float* __restrict__ w,
                             const float* __restrict__ b,
                             const float* __restrict__ ge,
                             const float* __restrict__ me) {
    int i = blockIdx.x * 256 + threadIdx.x;
    if (i >= NT * DM) return;
    int d = i & (DM - 1);
    int t = i >> 8;
    int l = t % SEQ;
    g_h[i] = x[t] * w[d] + b[d] + ge[l * DM + d] + me[d];
}

// LayerNorm over last dim (256); one block per token
__global__ void ln_kernel(const float* __restrict__ in, float* __restrict__ out,
                          const float* __restrict__ w, const float* __restrict__ b) {
    int t = blockIdx.x, d = threadIdx.x;
    float v = in[t * DM + d];
    float mean = blockReduceSum256(v) * (1.f / DM);
    float diff = v - mean;
    float var = blockReduceSum256(diff * diff) * (1.f / DM);
    out[t * DM + d] = diff * rsqrtf(var + 1e-5f) * w[d] + b[d];
}

// ---------------- SGEMM ----------------
// C[M,N] = A[M,K] @ W[N,K]^T, optional accumulate.
// 256 threads; micro-tile (BM/16)x(BN/16); register prefetch of next k-tile.
// NOTE: no minBlocksPerMultiprocessor clamp -> ptxas free up to 255 regs (no spill
// at BM=BN=128, ~111 regs, still 2 CTAs/SM by register count).
template<int BM, int BN, int ACCUM>
__global__ void __launch_bounds__(256)
sgemm_nt2(const float* __restrict__ A, const float* __restrict__ W,
          float* __restrict__ C, int M, int N, int K) {
    constexpr int BK = 16;
    constexpr int TM = BM / 16, TN = BN / 16;
    constexpr int NAL = BM / 64, NWL = BN / 64;
    __shared__ float As[BK][BM + 4];
    __shared__ float Ws[BK][BN + 4];

    const int tid = threadIdx.x;
    const int m0 = blockIdx.y * BM, n0 = blockIdx.x * BN;
    const int tx = tid & 15, ty = tid >> 4;
    const int lr = tid >> 2;             // 0..63
    const int lc = tid & 3;              // k-group (offset lc*4)

    float acc[TM][TN];
    #pragma unroll
    for (int i = 0; i < TM; i++)
        #pragma unroll
        for (int j = 0; j < TN; j++) acc[i][j] = 0.f;

    const float4 f4z = make_float4(0.f, 0.f, 0.f, 0.f);
    float4 pa[NAL], pw[NWL];

    // prefetch k-tile 0
    #pragma unroll
    for (int q = 0; q < NAL; q++) {
        int r = m0 + lr + 64 * q;
        pa[q] = (r < M) ? *reinterpret_cast<const float4*>(A + (size_t)r * K + lc * 4) : f4z;
    }
    #pragma unroll
    for (int q = 0; q < NWL; q++)
        pw[q] = *reinterpret_cast<const float4*>(W + (size_t)(n0 + lr + 64 * q) * K + lc * 4);

    for (int kt = 0; kt < K; kt += BK) {
        #pragma unroll
        for (int q = 0; q < NAL; q++) {
            As[lc * 4 + 0][lr + 64 * q] = pa[q].x;
            As[lc * 4 + 1][lr + 64 * q] = pa[q].y;
            As[lc * 4 + 2][lr + 64 * q] = pa[q].z;
            As[lc * 4 + 3][lr + 64 * q] = pa[q].w;
        }
        #pragma unroll
        for (int q = 0; q < NWL; q++) {
            Ws[lc * 4 + 0][lr + 64 * q] = pw[q].x;
            Ws[lc * 4 + 1][lr + 64 * q] = pw[q].y;
            Ws[lc * 4 + 2][lr + 64 * q] = pw[q].z;
            Ws[lc * 4 + 3][lr + 64 * q] = pw[q].w;
        }
        __syncthreads();

        if (kt + BK < K) {
            int kn = kt + BK;
            #pragma unroll
            for (int q = 0; q < NAL; q++) {
                int r = m0 + lr + 64 * q;
                pa[q] = (r < M) ? *reinterpret_cast<const float4*>(A + (size_t)r * K + kn + lc * 4) : f4z;
            }
            #pragma unroll
            for (int q = 0; q < NWL; q++)
                pw[q] = *reinterpret_cast<const float4*>(W + (size_t)(n0 + lr + 64 * q) * K + kn + lc * 4);
        }

        #pragma unroll
        for (int kk = 0; kk < BK; kk++) {
            float a[TM], w[TN];
            #pragma unroll
            for (int i4 = 0; i4 < TM; i4 += 4) {
                float4 v = *reinterpret_cast<const float4*>(&As[kk][ty * TM + i4]);
                a[i4 + 0] = v.x; a[i4 + 1] = v.y; a[i4 + 2] = v.z; a[i4 + 3] = v.w;
            }
            #pragma unroll
            for (int j4 = 0; j4 < TN; j4 += 4) {
                float4 v = *reinterpret_cast<const float4*>(&Ws[kk][tx * TN + j4]);
                w[j4 + 0] = v.x; w[j4 + 1] = v.y; w[j4 + 2] = v.z; w[j4 + 3] = v.w;
            }
            #pragma unroll
            for (int i = 0; i < TM; i++)
                #pragma unroll
                for (int j = 0; j < TN; j++)
                    acc[i][j] = fmaf(a[i], w[j], acc[i][j]);
        }
        __syncthreads();
    }

    #pragma unroll
    for (int i = 0; i < TM; i++) {
        int m = m0 + ty * TM + i;
        if (m >= M) continue;
        float* cr = C + (size_t)m * N + n0 + tx * TN;
        #pragma unroll
        for (int j4 = 0; j4 < TN; j4 += 4) {
            float4 v = make_float4(acc[i][j4], acc[i][j4 + 1], acc[i][j4 + 2], acc[i][j4 + 3]);
            if (ACCUM) {
                float4 o = *reinterpret_cast<const float4*>(cr + j4);
                v.x += o.x; v.y += o.y; v.z += o.z; v.w += o.w;
            }
            *reinterpret_cast<float4*>(cr + j4) = v;
        }
    }
}

// ---------------- fused conv+silu -> xproj -> dt (one block per token) ----------------
__global__ void __launch_bounds__(256)
mid_kernel(const float* __restrict__ cw, const float* __restrict__ cb,
           const float* __restrict__ xpw,
           const float* __restrict__ dtw, const float* __restrict__ dtb) {
    __shared__ float su[DI];
    __shared__ float sx[NXP];
    const int t = blockIdx.x;
    const int l = t % SEQ;
    const int tid = threadIdx.x;

    // conv + bias + SiLU
    #pragma unroll
    for (int d = tid; d < DI; d += 256) {
        float s = cb[d];
        #pragma unroll
        for (int k = 0; k < 4; k++) {
            int ls = l + k - 3;
            if (ls >= 0) s = fmaf(g_xz[(size_t)(t + k - 3) * (2 * DI) + d], cw[d * 4 + k], s);
        }
        float v = s / (1.f + __expf(-s));
        su[d] = v;
        g_u[(size_t)t * DI + d] = v;
    }
    __syncthreads();

    // xproj: 48 dots of length 512; warp w handles n = w*6..w*6+5
    {
        int wid = tid >> 5, lane = tid & 31;
        #pragma unroll
        for (int j = 0; j < 6; j++) {
            int n = wid * 6 + j;
            const float* wr = xpw + (size_t)n * DI;
            float s = 0.f;
            #pragma unroll
            for (int i = lane; i < DI; i += 32) s = fmaf(su[i], wr[i], s);
            #pragma unroll
            for (int o = 16; o > 0; o >>= 1) s += __shfl_xor_sync(0xffffffffu, s, o);
            if (lane == 0) {
                sx[n] = s;
                g_xdbc[(size_t)t * NXP + n] = s;
            }
        }
    }
    __syncthreads();

    // dt: softplus( sx[0:16] . dtw[d] + dtb[d] )
    #pragma unroll
    for (int d = tid; d < DI; d += 256) {
        const float* w = dtw + (size_t)d * DTR;
        float s = dtb[d];
        #pragma unroll
        for (int r = 0; r < DTR; r++) s = fmaf(sx[r], w[r], s);
        g_dt[(size_t)t * DI + d] = (s > 20.f) ? s : log1pf(__expf(s));
    }
}

// ---- fused chunked selective scan (single launch) ----
// Block = (b,d): 1024 blocks, 256 threads = 16 chunks x 16 n.
// Pass1 -> smem carries -> per-thread prefix (<=15 fma) -> pass2 emits gated y.
__global__ void __launch_bounds__(256)
scan_fused(const float* __restrict__ A_log, const float* __restrict__ Dv) {
    __shared__ float sap[NCHUNK][DS];   // chunk products
    __shared__ float ssn[NCHUNK][DS];   // chunk end-states

    const int d = blockIdx.x & (DI - 1);
    const int b = blockIdx.x >> 9;
    const int tid = threadIdx.x;
    const int n = tid & 15;
    const int c = tid >> 4;

    const float Ac = -__expf(A_log[d * DS + n]);
    const float Dd = Dv[d];
    const int t0 = b * SEQ + c * CLEN;

    // pass 1: local chunk scan (state from 0) + product of dA
    float state = 0.f, aprod = 1.f;
    #pragma unroll 5
    for (int l = 0; l < CLEN; l++) {
        int t = t0 + l;
        float dtv = g_dt[(size_t)t * DI + d];
        float uv  = g_u [(size_t)t * DI + d];
        float Bv  = g_xdbc[(size_t)t * NXP + DTR + n];
        float dA = __expf(dtv * Ac);
        aprod *= dA;
        state = fmaf(dA, state, dtv * Bv * uv);
    }
    sap[c][n] = aprod;
    ssn[c][n] = state;
    __syncthreads();

    // carry-in prefix for this chunk
    float carry = 0.f;
    for (int cc = 0; cc < c; cc++)
        carry = fmaf(sap[cc][n], carry, ssn[cc][n]);

    // pass 2: rescan from carry, emit gated y
    state = carry;
    #pragma unroll 5
    for (int l = 0; l < CLEN; l++) {
        int t = t0 + l;
        float dtv = g_dt[(size_t)t * DI + d];
        float uv  = g_u [(size_t)t * DI + d];
        float Bv  = g_xdbc[(size_t)t * NXP + DTR + n];
        float Cv  = g_xdbc[(size_t)t * NXP + DTR + DS + n];
        float dA = __expf(dtv * Ac);
        state = fmaf(dA, state, dtv * Bv * uv);
        float p = state * Cv;
        p += __shfl_xor_sync(0xffffffffu, p, 1, 16);
        p += __shfl_xor_sync(0xffffffffu, p, 2, 16);
        p += __shfl_xor_sync(0xffffffffu, p, 4, 16);
        p += __shfl_xor_sync(0xffffffffu, p, 8, 16);
        if (n == 0) {
            float z = g_xz[(size_t)t * (2 * DI) + DI + d];
            g_y[(size_t)t * DI + d] = (p + uv * Dd) * (z / (1.f + __expf(-z)));
        }
    }
}

// Final LN + head dot product; one block per token
__global__ void final_kernel(const float* __restrict__ fw, const float* __restrict__ fb,
                             const float* __restrict__ hw, const float* __restrict__ hb,
                             float* __restrict__ out) {
    int t = blockIdx.x, d = threadIdx.x;
    float v = g_h[t * DM + d];
    float mean = blockReduceSum256(v) * (1.f / DM);
    float diff = v - mean;
    float var = blockReduceSum256(diff * diff) * (1.f / DM);
    float nr = diff * rsqrtf(var + 1e-5f) * fw[d] + fb[d];
    float s = blockReduceSum256(nr * hw[d]);
    if (d == 0) out[t] = s + hb[0];
}

// ---------------- launch ----------------
extern "C" void kernel_launch(void* const* d_in, const int* in_sizes, int n_in,
                              void* d_out, int out_size) {
    const float* x         = (const float*)d_in[0];
    const float* bulk_in_w = (const float*)d_in[1];
    const float* bulk_in_b = (const float*)d_in[2];
    const float* gene_emb  = (const float*)d_in[3];
    const float* mod_emb   = (const float*)d_in[4];
    const float* ln_w      = (const float*)d_in[5];
    const float* ln_b      = (const float*)d_in[6];
    const float* in_proj_w = (const float*)d_in[7];
    const float* conv_w    = (const float*)d_in[8];
    const float* conv_b    = (const float*)d_in[9];
    const float* x_proj_w  = (const float*)d_in[10];
    const float* dt_proj_w = (const float*)d_in[11];
    const float* dt_proj_b = (const float*)d_in[12];
    const float* A_log     = (const float*)d_in[13];
    const float* Dvec      = (const float*)d_in[14];
    const float* out_proj_w= (const float*)d_in[15];
    const float* fin_w     = (const float*)d_in[16];
    const float* fin_b     = (const float*)d_in[17];
    const float* head_w    = (const float*)d_in[18];
    const float* head_b    = (const float*)d_in[19];
    float* out = (float*)d_out;

    float *p_h, *p_hn, *p_xz, *p_y;
    cudaGetSymbolAddress((void**)&p_h,  g_h);
    cudaGetSymbolAddress((void**)&p_hn, g_hn);
    cudaGetSymbolAddress((void**)&p_xz, g_xz);
    cudaGetSymbolAddress((void**)&p_y,  g_y);

    embed_kernel<<<(NT * DM + 255) / 256, 256>>>(x, bulk_in_w, bulk_in_b, gene_emb, mod_emb);

    for (int i = 0; i < NL; i++) {
        ln_kernel<<<NT, 256>>>(p_h, p_hn, ln_w + i * DM, ln_b + i * DM);

        // xz = hn @ in_proj_w^T   (M=4000, N=1024, K=256)  [128x128 tiles]
        sgemm_nt2<128, 128, 0><<<dim3((2 * DI) / 128, (NT + 127) / 128), 256>>>(
            p_hn, in_proj_w + (size_t)i * (2 * DI) * DM, p_xz, NT, 2 * DI, DM);

        mid_kernel<<<NT, 256>>>(conv_w + (size_t)i * DI * 4, conv_b + (size_t)i * DI,
                                x_proj_w + (size_t)i * NXP * DI,
                                dt_proj_w + (size_t)i * DI * DTR, dt_proj_b + (size_t)i * DI);

        scan_fused<<<BATCH * DI, 256>>>(A_log + (size_t)i * DI * DS, Dvec + (size_t)i * DI);

        // h += y @ out_proj_w^T   (M=4000, N=256, K=512)  [64x64 tiles]
        sgemm_nt2<64, 64, 1><<<dim3(DM / 64, (NT + 63) / 64), 256>>>(
            p_y, out_proj_w + (size_t)i * DM * DI, p_h, NT, DM, DI);
    }

    final_kernel<<<NT, 256>>>(fin_w, fin_b, head_w, head_b, out);
}